// round 1
// baseline (speedup 1.0000x reference)
#include <cuda_runtime.h>

#define TT   2048     // sequence length
#define RPLY 64       // accurate-replay window

__device__ __forceinline__ float tanh_fast(float x) {
    float y; asm("tanh.approx.f32 %0, %1;" : "=f"(y) : "f"(x)); return y;
}
__device__ __forceinline__ float ex2f_(float x) {
    float y; asm("ex2.approx.f32 %0, %1;" : "=f"(y) : "f"(x)); return y;
}
__device__ __forceinline__ float rcpf_(float x) {
    float y; asm("rcp.approx.f32 %0, %1;" : "=f"(y) : "f"(x)); return y;
}
// accurate tanh: 1 - 2/(exp2(2*log2e*x)+1); handles +-inf saturation correctly
__device__ __forceinline__ float tanh_acc(float x) {
    float e = ex2f_(x * 2.88539008177792681472f);   // 2*log2(e)
    float r = rcpf_(e + 1.0f);
    return fmaf(-2.0f, r, 1.0f);
}

extern "C" __global__ void __launch_bounds__(64, 1)
rnn_kernel(const float* __restrict__ x, const int* __restrict__ lengths,
           const float* __restrict__ Wih, const float* __restrict__ Whh,
           const float* __restrict__ bih, const float* __restrict__ bhh,
           const float* __restrict__ fcw, const float* __restrict__ fcb,
           float* __restrict__ out)
{
    const int b = blockIdx.x * 64 + threadIdx.x;

    const float wi0 = __ldg(Wih + 0), wi1 = __ldg(Wih + 1);
    const float w00 = __ldg(Whh + 0), w01 = __ldg(Whh + 1);
    const float w10 = __ldg(Whh + 2), w11 = __ldg(Whh + 3);
    const float c0  = __ldg(bih + 0) + __ldg(bhh + 0);
    const float c1  = __ldg(bih + 1) + __ldg(bhh + 1);

    const int len = __ldg(lengths + b);
    int stop = len - RPLY; if (stop < 0) stop = 0;

    // warp-uniform chunk bound: max 'stop' in warp, rounded up to 32
    int wmax = stop;
    #pragma unroll
    for (int o = 16; o; o >>= 1)
        wmax = max(wmax, __shfl_xor_sync(0xffffffffu, wmax, o));
    wmax = (wmax + 31) & ~31;

    const float4* xp4 = reinterpret_cast<const float4*>(x) + (size_t)b * (TT / 4);
    float h0 = 0.f, h1 = 0.f;

    if (wmax > 0) {
        // double-buffered 32-float chunks: prefetch next chunk while the
        // serial chain grinds through the current one (~900 cyc > DRAM 577)
        float4 buf[8];
        #pragma unroll
        for (int j = 0; j < 8; j++) buf[j] = __ldg(xp4 + j);

        for (int cb = 0; cb < wmax; cb += 32) {          // uniform per warp
            float4 nxt[8];
            const int nb = (cb + 32 < TT) ? ((cb + 32) >> 2) : 0; // clamp, stay in-bounds
            #pragma unroll
            for (int j = 0; j < 8; j++) nxt[j] = __ldg(xp4 + nb + j);

            const float* bf = reinterpret_cast<const float*>(buf);
            #pragma unroll
            for (int i = 0; i < 32; i++) {
                if (cb + i >= stop) break;               // per-lane early exit (SIMT)
                const float xv = bf[i];
                const float a0 = fmaf(xv, wi0, c0);
                const float a1 = fmaf(xv, wi1, c1);
                float u0 = fmaf(h1, w01, a0); u0 = fmaf(h0, w00, u0);
                float u1 = fmaf(h1, w11, a1); u1 = fmaf(h0, w10, u1);
                h0 = tanh_fast(u0);                      // chain: 4+4+16 (+8 MUFU rt)
                h1 = tanh_fast(u1);
            }
            #pragma unroll
            for (int j = 0; j < 8; j++) buf[j] = nxt[j];
        }
    }

    // ---- accurate replay of the final <=RPLY steps ----
    // Approx-phase error entering here is contracted by rho^RPLY (negligible);
    // replay itself uses ~1e-7/step tanh, so final state is reference-accurate.
    const float* xp = x + (size_t)b * TT;
    float rbuf[RPLY];
    #pragma unroll
    for (int r = 0; r < RPLY; r++) {                     // front-batched gather
        const int t = stop + r;
        rbuf[r] = (t < len) ? __ldg(xp + t) : 0.f;
    }
    #pragma unroll
    for (int r = 0; r < RPLY; r++) {
        if (stop + r >= len) break;
        const float xv = rbuf[r];
        const float a0 = fmaf(xv, wi0, c0);
        const float a1 = fmaf(xv, wi1, c1);
        float u0 = fmaf(h1, w01, a0); u0 = fmaf(h0, w00, u0);
        float u1 = fmaf(h1, w11, a1); u1 = fmaf(h0, w10, u1);
        h0 = tanh_acc(u0);
        h1 = tanh_acc(u1);
    }

    out[b] = fmaf(h0, __ldg(fcw + 0), fmaf(h1, __ldg(fcw + 1), __ldg(fcb + 0)));
}

extern "C" void kernel_launch(void* const* d_in, const int* in_sizes, int n_in,
                              void* d_out, int out_size) {
    const float* x   = (const float*)d_in[0];
    const int*   len = (const int*)d_in[1];
    const float* Wih = (const float*)d_in[2];
    const float* Whh = (const float*)d_in[3];
    const float* bih = (const float*)d_in[4];
    const float* bhh = (const float*)d_in[5];
    const float* fcw = (const float*)d_in[6];
    const float* fcb = (const float*)d_in[7];
    float* out = (float*)d_out;

    const int B = in_sizes[1];          // lengths element count = 8192
    rnn_kernel<<<B / 64, 64>>>(x, len, Wih, Whh, bih, bhh, fcw, fcb, out);
}